// round 7
// baseline (speedup 1.0000x reference)
#include <cuda_runtime.h>

// Problem constants (fixed shapes from reference)
#define NROWS   65536            // BATCH*SEQ = 64*1024
#define FEATD   512
#define NBINS   32

// Global-pool occurrence counting (reference's int32 semantics drop `env`:
// left_shift(env,32) on int32 == 0 in XLA, so combined == keys).
#define HASH_BITS 17
#define HASH_SZ   (1 << HASH_BITS)
#define DUP_CAP   1024

// ---------------- scratch (device globals; no allocation allowed) ----------
__device__ float g_psum[1024 * 512];
__device__ float g_psq [1024 * 512];
__device__ float g_psum2[16 * 512];
__device__ float g_psq2 [16 * 512];
__device__ float g_Pp  [512 * 32];     // P' = P / sigma   (row-major [feat][bin])
__device__ float g_biasp[16 * 32];     // per-block bias partials
__device__ unsigned int g_keys[NROWS];
__device__ unsigned long long g_hash[HASH_SZ];  // 0 = empty, else (1<<32)|key
__device__ unsigned int g_hcnt[HASH_SZ];        // total occurrences per slot
__device__ int g_slot[NROWS];                   // row -> slot
__device__ int g_dupn;
__device__ int g_dup[DUP_CAP];                  // rows whose key count > 1

// ---------------------------------------------------------------------------
// Kernel 1: per-feature partial sums / sums of squares + hash-table reset
// (131072 threads == HASH_SZ, so the zeroing rides along for free).
// grid 1024 x 128; block b handles rows [b*64, b*64+64), thread t owns
// feature quad [4t, 4t+4). Fully coalesced float4 streaming.
// ---------------------------------------------------------------------------
__global__ void __launch_bounds__(128) sums_kernel(const float* __restrict__ x) {
    int t = threadIdx.x;
    int g = blockIdx.x * 128 + t;
    g_hash[g] = 0ull;
    g_hcnt[g] = 0u;
    if (g == 0) g_dupn = 0;

    const float4* xg = (const float4*)x + (size_t)blockIdx.x * 64 * 128 + t;
    float sx = 0.f, sy = 0.f, sz = 0.f, sw = 0.f;
    float qx = 0.f, qy = 0.f, qz = 0.f, qw = 0.f;
#pragma unroll 8
    for (int r = 0; r < 64; r++) {
        float4 v = xg[(size_t)r * 128];
        sx += v.x; sy += v.y; sz += v.z; sw += v.w;
        qx = fmaf(v.x, v.x, qx); qy = fmaf(v.y, v.y, qy);
        qz = fmaf(v.z, v.z, qz); qw = fmaf(v.w, v.w, qw);
    }
    ((float4*)g_psum)[blockIdx.x * 128 + t] = make_float4(sx, sy, sz, sw);
    ((float4*)g_psq )[blockIdx.x * 128 + t] = make_float4(qx, qy, qz, qw);
}

// ---------------------------------------------------------------------------
// Kernel 2: fold 1024 partials -> 16 partials.
// grid 16 x 512: thread T -> (p = T/512, f = T%512), sums 64 input blocks.
// ---------------------------------------------------------------------------
__global__ void __launch_bounds__(512) midreduce_kernel() {
    int T = blockIdx.x * 512 + threadIdx.x;     // 0 .. 8191
    int p = T >> 9;
    int f = T & 511;
    float s = 0.f, q = 0.f;
#pragma unroll 8
    for (int i = 0; i < 64; i++) {
        int idx = ((p * 64 + i) << 9) + f;
        s += g_psum[idx];
        q += g_psq [idx];
    }
    g_psum2[T] = s;
    g_psq2 [T] = q;
}

// ---------------------------------------------------------------------------
// Kernel 3: stats + Pp + bias partials, fused.
// grid 16 x 1024: warp w of block b owns feature f = 32b + w.
// Lanes 0-15 load the 16 partials, fp64 shfl-tree reduce; lane 0 finalizes
// Welford-merged mean / inv-sigma (no div/sqrt: reciprocal consts + NR).
// Then lane j builds Pp[f][j] (coalesced) and block-reduces the bias.
// ---------------------------------------------------------------------------
__global__ void __launch_bounds__(1024) pp_kernel(const float* __restrict__ P) {
    __shared__ float sred[32][33];
    int tid = threadIdx.x, warp = tid >> 5, lane = tid & 31;
    int f = blockIdx.x * 32 + warp;

    double sv = 0.0, qv = 0.0;
    if (lane < 16) {
        sv = (double)g_psum2[(lane << 9) + f];
        qv = (double)g_psq2 [(lane << 9) + f];
    }
#pragma unroll
    for (int off = 8; off > 0; off >>= 1) {
        sv += __shfl_down_sync(0xffffffffu, sv, off);
        qv += __shfl_down_sync(0xffffffffu, qv, off);
    }
    float meanf = 0.f, isig = 0.f;
    if (lane == 0) {
        const double Nd      = 65536.0;
        const double INV_N   = 1.0 / 65536.0;
        const double INV_NM1 = 1.0 / 65535.0;
        const double INV_TOT = 1.0 / 65536.0001;           // 1/(1e-4 + N)
        const double RATIO   = 65536.0 * INV_TOT;          // N/tot
        const double C1      = 1e-4 * 65536.0 * INV_TOT;   // eps*N/tot
        double bm   = sv * INV_N;
        double bv   = (qv - Nd * bm * bm) * INV_NM1;       // unbiased var
        double mean = bm * RATIO;
        double var  = (1e-4 + bv * Nd + bm * bm * C1) * INV_TOT;
        double v    = var + 1e-8;
        double r = (double)rsqrtf((float)v);               // + 1 NR step
        r = r * (1.5 - 0.5 * v * r * r);
        meanf = (float)mean;
        isig  = (float)r;
    }
    meanf = __shfl_sync(0xffffffffu, meanf, 0);
    isig  = __shfl_sync(0xffffffffu, isig,  0);

    float pp = P[f * 32 + lane] * isig;
    g_Pp[f * 32 + lane] = pp;
    sred[warp][lane] = meanf * pp;
    __syncthreads();
    if (warp == 0) {
        float b = 0.f;
#pragma unroll
        for (int w = 0; w < 32; w++) b += sred[w][lane];
        g_biasp[blockIdx.x * 32 + lane] = b;
    }
}

// ---------------------------------------------------------------------------
// Kernel 4: projection + sign-bit keys + hash insert (fused), double-buffered.
//   key[i] = ballot_j( x[i] . Pp[:,j] - bias_j > 0 )
// Next tile is staged in registers during the fma2 phase (hides DRAM latency);
// the hash insert runs after the psum-WAR barrier so its ~400-cycle atomic
// latency hides under the next batch's compute.
// ---------------------------------------------------------------------------
#define P3_CH   64
#define P3_NW   8
#define P3_RB   8
#define P3_NBATCH (NROWS / P3_RB)    // 8192

__global__ void __launch_bounds__(256, 2) proj_kernel(const float* __restrict__ x) {
    __shared__ float xs[2][P3_RB * FEATD];         // 2 x 16 KB tiles
    __shared__ float psum[P3_RB][P3_NW][NBINS];    // 8 KB partials
    __shared__ float sbias[NBINS];

    int tid  = threadIdx.x;
    int warp = tid >> 5;
    int lane = tid & 31;

    if (tid < NBINS) {
        float b = 0.f;
#pragma unroll
        for (int p = 0; p < 16; p++) b += g_biasp[p * 32 + tid];
        sbias[tid] = b;
    }

    // register-resident Pp chunk: ppd[i] = (Pp[k0+2i][lane], Pp[k0+2i+1][lane])
    unsigned long long ppd[P3_CH / 2];
    int k0 = warp * P3_CH;
#pragma unroll
    for (int i = 0; i < P3_CH / 2; i++) {
        float a = g_Pp[(k0 + 2 * i)     * NBINS + lane];
        float b = g_Pp[(k0 + 2 * i + 1) * NBINS + lane];
        asm("mov.b64 %0, {%1, %2};" : "=l"(ppd[i]) : "f"(a), "f"(b));
    }

    // prologue: load first tile
    {
        const float4* xg = (const float4*)(x + (size_t)blockIdx.x * P3_RB * FEATD);
        float4* xs4 = (float4*)xs[0];
#pragma unroll
        for (int i = 0; i < 4; i++) xs4[tid + 256 * i] = xg[tid + 256 * i];
    }
    __syncthreads();

    int cur = 0;
    for (int batch = blockIdx.x; batch < P3_NBATCH; batch += gridDim.x) {
        int nb = batch + gridDim.x;
        float4 stage0, stage1, stage2, stage3;
        if (nb < P3_NBATCH) {
            const float4* xg = (const float4*)(x + (size_t)nb * P3_RB * FEATD);
            stage0 = xg[tid];       stage1 = xg[tid + 256];
            stage2 = xg[tid + 512]; stage3 = xg[tid + 768];
        }

        const float* xsc = xs[cur];
#pragma unroll
        for (int r = 0; r < P3_RB; r++) {
            const ulonglong2* xp = (const ulonglong2*)(xsc + r * FEATD + k0);
            unsigned long long a0 = 0ull, a1 = 0ull;   // (0.f,0.f) packed
#pragma unroll
            for (int i = 0; i < P3_CH / 4; i++) {
                ulonglong2 v = xp[i];                   // LDS.128 broadcast
                asm("fma.rn.f32x2 %0, %1, %2, %0;"
                    : "+l"(a0) : "l"(v.x), "l"(ppd[2 * i]));
                asm("fma.rn.f32x2 %0, %1, %2, %0;"
                    : "+l"(a1) : "l"(v.y), "l"(ppd[2 * i + 1]));
            }
            unsigned long long at;
            asm("add.rn.f32x2 %0, %1, %2;" : "=l"(at) : "l"(a0), "l"(a1));
            float lo, hi;
            asm("mov.b64 {%0, %1}, %2;" : "=f"(lo), "=f"(hi) : "l"(at));
            psum[r][warp][lane] = lo + hi;
        }

        if (nb < P3_NBATCH) {
            float4* xs4 = (float4*)xs[cur ^ 1];
            xs4[tid]       = stage0; xs4[tid + 256] = stage1;
            xs4[tid + 512] = stage2; xs4[tid + 768] = stage3;
        }
        __syncthreads();   // psum complete + next tile committed

        // warp r reduces row r across the 8 K-chunks, ballots the key
        int row = batch * P3_RB + warp;
        float s = 0.f;
#pragma unroll
        for (int c = 0; c < P3_NW; c++) s += psum[warp][c][lane];
        unsigned key = __ballot_sync(0xffffffffu, s > sbias[lane]);

        __syncthreads();   // psum WAR-safe for next iteration

        // deferred hash insert: latency hides under next batch's compute
        if (lane == 0) {
            g_keys[row] = key;
            unsigned long long tag = (1ull << 32) | (unsigned long long)key;
            unsigned h = (key * 2654435761u) >> (32 - HASH_BITS);
            for (;;) {
                unsigned long long prev = atomicCAS(&g_hash[h], 0ull, tag);
                if (prev == 0ull || prev == tag) {
                    atomicAdd(&g_hcnt[h], 1u);
                    g_slot[row] = (int)h;
                    break;
                }
                h = (h + 1) & (HASH_SZ - 1);
            }
        }
        cur ^= 1;
    }
}

// ---------------------------------------------------------------------------
// Kernel 5: emit rewards for unique keys (count==1 -> 1.0); collect dup rows.
// ---------------------------------------------------------------------------
__global__ void __launch_bounds__(256) emit_kernel(float* __restrict__ out) {
    int i = blockIdx.x * 256 + threadIdx.x;
    if (g_hcnt[g_slot[i]] == 1u) {
        out[i] = 1.0f;
    } else {
        int d = atomicAdd(&g_dupn, 1);
        if (d < DUP_CAP) g_dup[d] = i;
    }
}

// ---------------------------------------------------------------------------
// Kernel 6: exact occurrence rank for duplicated rows (rare; ~2 expected).
// grid 16 looping blocks: occ = #{ j <= i : key_j == key_i }.
// ---------------------------------------------------------------------------
__global__ void __launch_bounds__(256) dupfix_kernel(float* __restrict__ out) {
    __shared__ int red[256];
    int n = g_dupn;
    if (n > DUP_CAP) n = DUP_CAP;
    int t = threadIdx.x;
    for (int d = blockIdx.x; d < n; d += gridDim.x) {
        int i = g_dup[d];
        unsigned key = g_keys[i];
        int c = 0;
        for (int j = t; j <= i; j += 256) c += (g_keys[j] == key) ? 1 : 0;
        red[t] = c;
        __syncthreads();
#pragma unroll
        for (int off = 128; off > 0; off >>= 1) {
            if (t < off) red[t] += red[t + off];
            __syncthreads();
        }
        if (t == 0) out[i] = rsqrtf((float)red[0]);
        __syncthreads();   // red reuse guard
    }
}

// ---------------------------------------------------------------------------
extern "C" void kernel_launch(void* const* d_in, const int* in_sizes, int n_in,
                              void* d_out, int out_size) {
    const float* x = (const float*)d_in[0];   // features  [64,1024,512]
    const float* P = (const float*)d_in[1];   // projection [512,32]
    if (n_in >= 2 && in_sizes[0] < in_sizes[1]) {   // defensive order check
        const float* t = x; x = P; P = t;
    }
    float* out = (float*)d_out;

    sums_kernel     <<<1024, 128>>>(x);
    midreduce_kernel<<<16,   512>>>();
    pp_kernel       <<<16,   1024>>>(P);
    proj_kernel     <<<304,  256>>>(x);
    emit_kernel     <<<NROWS / 256, 256>>>(out);
    dupfix_kernel   <<<16,   256>>>(out);
}

// round 8
// speedup vs baseline: 1.1145x; 1.1145x over previous
#include <cuda_runtime.h>

// Problem constants (fixed shapes from reference)
#define NROWS   65536            // BATCH*SEQ = 64*1024
#define FEATD   512
#define NBINS   32

// Global-pool occurrence counting (reference's int32 semantics drop `env`:
// left_shift(env,32) on int32 == 0 in XLA, so combined == keys).
#define HASH_BITS 17
#define HASH_SZ   (1 << HASH_BITS)
#define DUP_CAP   1024

// ---------------- scratch (device globals; no allocation allowed) ----------
__device__ float g_psum[1024 * 512];
__device__ float g_psq [1024 * 512];
__device__ float g_psum2[16 * 512];
__device__ float g_psq2 [16 * 512];
__device__ float g_Pp  [512 * 32];     // P' = P / sigma   (row-major [feat][bin])
__device__ float g_biasp[16 * 32];     // per-block bias partials
__device__ unsigned int g_keys[NROWS];
__device__ unsigned long long g_hash[HASH_SZ];  // 0 = empty, else (1<<32)|key
__device__ unsigned int g_hcnt[HASH_SZ];        // total occurrences per slot
__device__ int g_slot[NROWS];                   // row -> slot
__device__ int g_dupn;
__device__ int g_dup[DUP_CAP];                  // rows whose key count > 1

// ---------------------------------------------------------------------------
// Kernel 1: per-feature partial sums / sums of squares + hash-table reset
// (131072 threads == HASH_SZ, so the zeroing rides along for free).
// ---------------------------------------------------------------------------
__global__ void __launch_bounds__(128) sums_kernel(const float* __restrict__ x) {
    int t = threadIdx.x;
    int g = blockIdx.x * 128 + t;
    g_hash[g] = 0ull;
    g_hcnt[g] = 0u;
    if (g == 0) g_dupn = 0;

    const float4* xg = (const float4*)x + (size_t)blockIdx.x * 64 * 128 + t;
    float sx = 0.f, sy = 0.f, sz = 0.f, sw = 0.f;
    float qx = 0.f, qy = 0.f, qz = 0.f, qw = 0.f;
#pragma unroll 8
    for (int r = 0; r < 64; r++) {
        float4 v = xg[(size_t)r * 128];
        sx += v.x; sy += v.y; sz += v.z; sw += v.w;
        qx = fmaf(v.x, v.x, qx); qy = fmaf(v.y, v.y, qy);
        qz = fmaf(v.z, v.z, qz); qw = fmaf(v.w, v.w, qw);
    }
    ((float4*)g_psum)[blockIdx.x * 128 + t] = make_float4(sx, sy, sz, sw);
    ((float4*)g_psq )[blockIdx.x * 128 + t] = make_float4(qx, qy, qz, qw);
}

// ---------------------------------------------------------------------------
// Kernel 2: fold 1024 partials -> 16 partials.
// ---------------------------------------------------------------------------
__global__ void __launch_bounds__(512) midreduce_kernel() {
    int T = blockIdx.x * 512 + threadIdx.x;     // 0 .. 8191
    int p = T >> 9;
    int f = T & 511;
    float s = 0.f, q = 0.f;
#pragma unroll 8
    for (int i = 0; i < 64; i++) {
        int idx = ((p * 64 + i) << 9) + f;
        s += g_psum[idx];
        q += g_psq [idx];
    }
    g_psum2[T] = s;
    g_psq2 [T] = q;
}

// ---------------------------------------------------------------------------
// Kernel 3: stats + Pp + bias partials, fused (warp-per-feature).
// ---------------------------------------------------------------------------
__global__ void __launch_bounds__(1024) pp_kernel(const float* __restrict__ P) {
    __shared__ float sred[32][33];
    int tid = threadIdx.x, warp = tid >> 5, lane = tid & 31;
    int f = blockIdx.x * 32 + warp;

    double sv = 0.0, qv = 0.0;
    if (lane < 16) {
        sv = (double)g_psum2[(lane << 9) + f];
        qv = (double)g_psq2 [(lane << 9) + f];
    }
#pragma unroll
    for (int off = 8; off > 0; off >>= 1) {
        sv += __shfl_down_sync(0xffffffffu, sv, off);
        qv += __shfl_down_sync(0xffffffffu, qv, off);
    }
    float meanf = 0.f, isig = 0.f;
    if (lane == 0) {
        const double Nd      = 65536.0;
        const double INV_N   = 1.0 / 65536.0;
        const double INV_NM1 = 1.0 / 65535.0;
        const double INV_TOT = 1.0 / 65536.0001;           // 1/(1e-4 + N)
        const double RATIO   = 65536.0 * INV_TOT;          // N/tot
        const double C1      = 1e-4 * 65536.0 * INV_TOT;   // eps*N/tot
        double bm   = sv * INV_N;
        double bv   = (qv - Nd * bm * bm) * INV_NM1;       // unbiased var
        double mean = bm * RATIO;
        double var  = (1e-4 + bv * Nd + bm * bm * C1) * INV_TOT;
        double v    = var + 1e-8;
        double r = (double)rsqrtf((float)v);               // + 1 NR step
        r = r * (1.5 - 0.5 * v * r * r);
        meanf = (float)mean;
        isig  = (float)r;
    }
    meanf = __shfl_sync(0xffffffffu, meanf, 0);
    isig  = __shfl_sync(0xffffffffu, isig,  0);

    float pp = P[f * 32 + lane] * isig;
    g_Pp[f * 32 + lane] = pp;
    sred[warp][lane] = meanf * pp;
    __syncthreads();
    if (warp == 0) {
        float b = 0.f;
#pragma unroll
        for (int w = 0; w < 32; w++) b += sred[w][lane];
        g_biasp[blockIdx.x * 32 + lane] = b;
    }
}

// ---------------------------------------------------------------------------
// hash insert (lane-0 helper): same key always resolves to the same slot.
// ---------------------------------------------------------------------------
__device__ __forceinline__ void hash_insert(int row, unsigned key) {
    g_keys[row] = key;
    unsigned long long tag = (1ull << 32) | (unsigned long long)key;
    unsigned h = (key * 2654435761u) >> (32 - HASH_BITS);
    for (;;) {
        unsigned long long prev = atomicCAS(&g_hash[h], 0ull, tag);
        if (prev == 0ull || prev == tag) {
            atomicAdd(&g_hcnt[h], 1u);
            g_slot[row] = (int)h;
            break;
        }
        h = (h + 1) & (HASH_SZ - 1);
    }
}

// ---------------------------------------------------------------------------
// Kernel 4: projection + sign-bit keys + hash insert, cp.async double-buffered.
//   key[i] = ballot_j( x[i] . Pp[:,j] - bias_j > 0 )
// 16-row tiles; next tile streams GMEM->SMEM via cp.async.cg while the fma2
// phase runs (no register staging -> ~90 regs). Hash inserts for iteration k
// are issued at the top of iteration k+1 so CAS latency hides under compute.
// ---------------------------------------------------------------------------
#define P3_CH   64
#define P3_NW   8
#define P3_RB   16
#define P3_NBATCH (NROWS / P3_RB)    // 4096

__global__ void __launch_bounds__(256, 2) proj_kernel(const float* __restrict__ x) {
    __shared__ float xs[2][P3_RB * FEATD];         // 2 x 32 KB tiles
    __shared__ float psum[P3_RB][P3_NW][NBINS];    // 16 KB partials
    __shared__ float sbias[NBINS];

    int tid  = threadIdx.x;
    int warp = tid >> 5;
    int lane = tid & 31;

    if (tid < NBINS) {
        float b = 0.f;
#pragma unroll
        for (int p = 0; p < 16; p++) b += g_biasp[p * 32 + tid];
        sbias[tid] = b;
    }

    // register-resident Pp chunk: ppd[i] = (Pp[k0+2i][lane], Pp[k0+2i+1][lane])
    unsigned long long ppd[P3_CH / 2];
    int k0 = warp * P3_CH;
#pragma unroll
    for (int i = 0; i < P3_CH / 2; i++) {
        float a = g_Pp[(k0 + 2 * i)     * NBINS + lane];
        float b = g_Pp[(k0 + 2 * i + 1) * NBINS + lane];
        asm("mov.b64 %0, {%1, %2};" : "=l"(ppd[i]) : "f"(a), "f"(b));
    }

    unsigned sb0 = (unsigned)__cvta_generic_to_shared(xs[0]);
    unsigned sb1 = (unsigned)__cvta_generic_to_shared(xs[1]);

    // prologue: stream first tile
    {
        const float4* xg = (const float4*)(x + (size_t)blockIdx.x * P3_RB * FEATD);
#pragma unroll
        for (int i = 0; i < 8; i++) {
            unsigned d = sb0 + (tid + 256 * i) * 16;
            asm volatile("cp.async.cg.shared.global [%0], [%1], 16;"
                         :: "r"(d), "l"(xg + tid + 256 * i));
        }
        asm volatile("cp.async.commit_group;");
        asm volatile("cp.async.wait_group 0;" ::: "memory");
    }
    __syncthreads();

    int cur = 0;
    int prow = -1;                  // pending rows (prow, prow+8), keys pk0/pk1
    unsigned pk0 = 0, pk1 = 0;

    for (int batch = blockIdx.x; batch < P3_NBATCH; batch += gridDim.x) {
        int nb = batch + gridDim.x;
        if (nb < P3_NBATCH) {
            const float4* xg = (const float4*)(x + (size_t)nb * P3_RB * FEATD);
            unsigned dst = cur ? sb0 : sb1;
#pragma unroll
            for (int i = 0; i < 8; i++) {
                unsigned d = dst + (tid + 256 * i) * 16;
                asm volatile("cp.async.cg.shared.global [%0], [%1], 16;"
                             :: "r"(d), "l"(xg + tid + 256 * i));
            }
            asm volatile("cp.async.commit_group;");
        }

        // pending inserts: atomic latency hides under this iter's fma phase
        if (lane == 0 && prow >= 0) {
            hash_insert(prow,     pk0);
            hash_insert(prow + 8, pk1);
        }

        const float* xsc = xs[cur];
#pragma unroll
        for (int r = 0; r < P3_RB; r++) {
            const ulonglong2* xp = (const ulonglong2*)(xsc + r * FEATD + k0);
            unsigned long long a0 = 0ull, a1 = 0ull;   // (0.f,0.f) packed
#pragma unroll
            for (int i = 0; i < P3_CH / 4; i++) {
                ulonglong2 v = xp[i];                   // LDS.128 broadcast
                asm("fma.rn.f32x2 %0, %1, %2, %0;"
                    : "+l"(a0) : "l"(v.x), "l"(ppd[2 * i]));
                asm("fma.rn.f32x2 %0, %1, %2, %0;"
                    : "+l"(a1) : "l"(v.y), "l"(ppd[2 * i + 1]));
            }
            unsigned long long at;
            asm("add.rn.f32x2 %0, %1, %2;" : "=l"(at) : "l"(a0), "l"(a1));
            float lo, hi;
            asm("mov.b64 {%0, %1}, %2;" : "=f"(lo), "=f"(hi) : "l"(at));
            psum[r][warp][lane] = lo + hi;
        }
        __syncthreads();   // psum complete

        // warp reduces rows (warp, warp+8) across the 8 K-chunks, ballots keys
        float s0 = 0.f, s1 = 0.f;
#pragma unroll
        for (int c = 0; c < P3_NW; c++) {
            s0 += psum[warp][c][lane];
            s1 += psum[warp + 8][c][lane];
        }
        pk0 = __ballot_sync(0xffffffffu, s0 > sbias[lane]);
        pk1 = __ballot_sync(0xffffffffu, s1 > sbias[lane]);
        prow = batch * P3_RB + warp;

        if (nb < P3_NBATCH)
            asm volatile("cp.async.wait_group 0;" ::: "memory");
        __syncthreads();   // next tile visible + psum WAR-safe
        cur ^= 1;
    }
    // flush last pending inserts
    if (lane == 0 && prow >= 0) {
        hash_insert(prow,     pk0);
        hash_insert(prow + 8, pk1);
    }
}

// ---------------------------------------------------------------------------
// Kernel 5: emit rewards for unique keys (count==1 -> 1.0); collect dup rows.
// ---------------------------------------------------------------------------
__global__ void __launch_bounds__(256) emit_kernel(float* __restrict__ out) {
    int i = blockIdx.x * 256 + threadIdx.x;
    if (g_hcnt[g_slot[i]] == 1u) {
        out[i] = 1.0f;
    } else {
        int d = atomicAdd(&g_dupn, 1);
        if (d < DUP_CAP) g_dup[d] = i;
    }
}

// ---------------------------------------------------------------------------
// Kernel 6: exact occurrence rank for duplicated rows (rare; ~2 expected).
// ---------------------------------------------------------------------------
__global__ void __launch_bounds__(256) dupfix_kernel(float* __restrict__ out) {
    __shared__ int red[256];
    int n = g_dupn;
    if (n > DUP_CAP) n = DUP_CAP;
    int t = threadIdx.x;
    for (int d = blockIdx.x; d < n; d += gridDim.x) {
        int i = g_dup[d];
        unsigned key = g_keys[i];
        int c = 0;
        for (int j = t; j <= i; j += 256) c += (g_keys[j] == key) ? 1 : 0;
        red[t] = c;
        __syncthreads();
#pragma unroll
        for (int off = 128; off > 0; off >>= 1) {
            if (t < off) red[t] += red[t + off];
            __syncthreads();
        }
        if (t == 0) out[i] = rsqrtf((float)red[0]);
        __syncthreads();   // red reuse guard
    }
}

// ---------------------------------------------------------------------------
extern "C" void kernel_launch(void* const* d_in, const int* in_sizes, int n_in,
                              void* d_out, int out_size) {
    const float* x = (const float*)d_in[0];   // features  [64,1024,512]
    const float* P = (const float*)d_in[1];   // projection [512,32]
    if (n_in >= 2 && in_sizes[0] < in_sizes[1]) {   // defensive order check
        const float* t = x; x = P; P = t;
    }
    float* out = (float*)d_out;

    sums_kernel     <<<1024, 128>>>(x);
    midreduce_kernel<<<16,   512>>>();
    pp_kernel       <<<16,   1024>>>(P);
    proj_kernel     <<<296,  256>>>(x);
    emit_kernel     <<<NROWS / 256, 256>>>(out);
    dupfix_kernel   <<<16,   256>>>(out);
}

// round 9
// speedup vs baseline: 1.1841x; 1.0625x over previous
#include <cuda_runtime.h>

// Problem constants (fixed shapes from reference)
#define NROWS   65536            // BATCH*SEQ = 64*1024
#define FEATD   512
#define NBINS   32

// Global-pool occurrence counting (reference's int32 semantics drop `env`:
// left_shift(env,32) on int32 == 0 in XLA, so combined == keys).
#define HASH_BITS 17
#define HASH_SZ   (1 << HASH_BITS)
#define DUP_CAP   1024

// ---------------- scratch (device globals; no allocation allowed) ----------
__device__ float g_psum[1024 * 512];
__device__ float g_psq [1024 * 512];
__device__ float g_psum2[16 * 512];
__device__ float g_psq2 [16 * 512];
__device__ float g_Pp  [512 * 32];     // P' = P / sigma   (row-major [feat][bin])
__device__ float g_biasp[16 * 32];     // per-block bias partials
__device__ unsigned int g_keys[NROWS];
__device__ unsigned long long g_hash[HASH_SZ];  // 0 = empty, else (1<<32)|key
__device__ unsigned int g_hcnt[HASH_SZ];        // total occurrences per slot
__device__ int g_slot[NROWS];                   // row -> slot
__device__ int g_dupn;
__device__ int g_dup[DUP_CAP];                  // rows whose key count > 1

// ---------------------------------------------------------------------------
// Kernel 1: per-feature partial sums / sums of squares + hash-table reset
// (131072 threads == HASH_SZ, so the zeroing rides along for free).
// ---------------------------------------------------------------------------
__global__ void __launch_bounds__(128) sums_kernel(const float* __restrict__ x) {
    int t = threadIdx.x;
    int g = blockIdx.x * 128 + t;
    g_hash[g] = 0ull;
    g_hcnt[g] = 0u;
    if (g == 0) g_dupn = 0;

    const float4* xg = (const float4*)x + (size_t)blockIdx.x * 64 * 128 + t;
    float sx = 0.f, sy = 0.f, sz = 0.f, sw = 0.f;
    float qx = 0.f, qy = 0.f, qz = 0.f, qw = 0.f;
#pragma unroll 8
    for (int r = 0; r < 64; r++) {
        float4 v = xg[(size_t)r * 128];
        sx += v.x; sy += v.y; sz += v.z; sw += v.w;
        qx = fmaf(v.x, v.x, qx); qy = fmaf(v.y, v.y, qy);
        qz = fmaf(v.z, v.z, qz); qw = fmaf(v.w, v.w, qw);
    }
    ((float4*)g_psum)[blockIdx.x * 128 + t] = make_float4(sx, sy, sz, sw);
    ((float4*)g_psq )[blockIdx.x * 128 + t] = make_float4(qx, qy, qz, qw);
}

// ---------------------------------------------------------------------------
// Kernel 2: fold 1024 partials -> 16 partials.
// ---------------------------------------------------------------------------
__global__ void __launch_bounds__(512) midreduce_kernel() {
    int T = blockIdx.x * 512 + threadIdx.x;     // 0 .. 8191
    int p = T >> 9;
    int f = T & 511;
    float s = 0.f, q = 0.f;
#pragma unroll 8
    for (int i = 0; i < 64; i++) {
        int idx = ((p * 64 + i) << 9) + f;
        s += g_psum[idx];
        q += g_psq [idx];
    }
    g_psum2[T] = s;
    g_psq2 [T] = q;
}

// ---------------------------------------------------------------------------
// Kernel 3: stats + Pp + bias partials, fused (warp-per-feature).
// ---------------------------------------------------------------------------
__global__ void __launch_bounds__(1024) pp_kernel(const float* __restrict__ P) {
    __shared__ float sred[32][33];
    int tid = threadIdx.x, warp = tid >> 5, lane = tid & 31;
    int f = blockIdx.x * 32 + warp;

    double sv = 0.0, qv = 0.0;
    if (lane < 16) {
        sv = (double)g_psum2[(lane << 9) + f];
        qv = (double)g_psq2 [(lane << 9) + f];
    }
#pragma unroll
    for (int off = 8; off > 0; off >>= 1) {
        sv += __shfl_down_sync(0xffffffffu, sv, off);
        qv += __shfl_down_sync(0xffffffffu, qv, off);
    }
    float meanf = 0.f, isig = 0.f;
    if (lane == 0) {
        const double Nd      = 65536.0;
        const double INV_N   = 1.0 / 65536.0;
        const double INV_NM1 = 1.0 / 65535.0;
        const double INV_TOT = 1.0 / 65536.0001;           // 1/(1e-4 + N)
        const double RATIO   = 65536.0 * INV_TOT;          // N/tot
        const double C1      = 1e-4 * 65536.0 * INV_TOT;   // eps*N/tot
        double bm   = sv * INV_N;
        double bv   = (qv - Nd * bm * bm) * INV_NM1;       // unbiased var
        double mean = bm * RATIO;
        double var  = (1e-4 + bv * Nd + bm * bm * C1) * INV_TOT;
        double v    = var + 1e-8;
        double r = (double)rsqrtf((float)v);               // + 1 NR step
        r = r * (1.5 - 0.5 * v * r * r);
        meanf = (float)mean;
        isig  = (float)r;
    }
    meanf = __shfl_sync(0xffffffffu, meanf, 0);
    isig  = __shfl_sync(0xffffffffu, isig,  0);

    float pp = P[f * 32 + lane] * isig;
    g_Pp[f * 32 + lane] = pp;
    sred[warp][lane] = meanf * pp;
    __syncthreads();
    if (warp == 0) {
        float b = 0.f;
#pragma unroll
        for (int w = 0; w < 32; w++) b += sred[w][lane];
        g_biasp[blockIdx.x * 32 + lane] = b;
    }
}

// ---------------------------------------------------------------------------
// hash insert (lane-0 helper): same key always resolves to the same slot.
// ---------------------------------------------------------------------------
__device__ __forceinline__ void hash_insert(int row, unsigned key) {
    g_keys[row] = key;
    unsigned long long tag = (1ull << 32) | (unsigned long long)key;
    unsigned h = (key * 2654435761u) >> (32 - HASH_BITS);
    for (;;) {
        unsigned long long prev = atomicCAS(&g_hash[h], 0ull, tag);
        if (prev == 0ull || prev == tag) {
            atomicAdd(&g_hcnt[h], 1u);
            g_slot[row] = (int)h;
            break;
        }
        h = (h + 1) & (HASH_SZ - 1);
    }
}

// ---------------------------------------------------------------------------
// Kernel 4: projection + sign-bit keys + hash insert.
//   key[i] = ballot_j( x[i] . Pp[:,j] - bias_j > 0 )
// 512 threads = 16 warps; warp w owns K-chunk [32w, 32w+32) (ppd = 32 regs,
// launch_bounds(512,2) -> 64-reg target -> 32 warps/SM). 16-row tiles double-
// buffered via cp.async.cg; hash inserts deferred one iteration so CAS
// latency hides under the fma2 phase. Dynamic smem: 2x32KB tiles + 32KB psum.
// ---------------------------------------------------------------------------
#define P3_CH   32
#define P3_NW   16
#define P3_RB   16
#define P3_NBATCH (NROWS / P3_RB)    // 4096
#define P3_SMEM  ((8192 * 3 + 32) * 4)

__global__ void __launch_bounds__(512, 2) proj_kernel(const float* __restrict__ x) {
    extern __shared__ float smem[];
    float* xs0   = smem;            // 8192 floats (16 rows x 512)
    float* xs1   = smem + 8192;     // 8192 floats
    float* psum  = smem + 16384;    // 8192 floats = [row][chunk][bin]
    float* sbias = smem + 24576;    // 32 floats

    int tid  = threadIdx.x;
    int warp = tid >> 5;
    int lane = tid & 31;

    if (tid < NBINS) {
        float b = 0.f;
#pragma unroll
        for (int p = 0; p < 16; p++) b += g_biasp[p * 32 + tid];
        sbias[tid] = b;
    }

    // register-resident Pp chunk: ppd[i] = (Pp[k0+2i][lane], Pp[k0+2i+1][lane])
    unsigned long long ppd[P3_CH / 2];
    int k0 = warp * P3_CH;
#pragma unroll
    for (int i = 0; i < P3_CH / 2; i++) {
        float a = g_Pp[(k0 + 2 * i)     * NBINS + lane];
        float b = g_Pp[(k0 + 2 * i + 1) * NBINS + lane];
        asm("mov.b64 %0, {%1, %2};" : "=l"(ppd[i]) : "f"(a), "f"(b));
    }

    unsigned sb0 = (unsigned)__cvta_generic_to_shared(xs0);
    unsigned sb1 = (unsigned)__cvta_generic_to_shared(xs1);

    // prologue: stream first tile (2048 float4, 512 threads -> 4 each)
    {
        const float4* xg = (const float4*)(x + (size_t)blockIdx.x * P3_RB * FEATD);
#pragma unroll
        for (int i = 0; i < 4; i++) {
            unsigned d = sb0 + (tid + 512 * i) * 16;
            asm volatile("cp.async.cg.shared.global [%0], [%1], 16;"
                         :: "r"(d), "l"(xg + tid + 512 * i));
        }
        asm volatile("cp.async.commit_group;");
        asm volatile("cp.async.wait_group 0;" ::: "memory");
    }
    __syncthreads();

    int cur = 0;
    int prow = -1;                  // pending row, key pk (one per warp)
    unsigned pk = 0;

    for (int batch = blockIdx.x; batch < P3_NBATCH; batch += gridDim.x) {
        int nb = batch + gridDim.x;
        if (nb < P3_NBATCH) {
            const float4* xg = (const float4*)(x + (size_t)nb * P3_RB * FEATD);
            unsigned dst = cur ? sb0 : sb1;
#pragma unroll
            for (int i = 0; i < 4; i++) {
                unsigned d = dst + (tid + 512 * i) * 16;
                asm volatile("cp.async.cg.shared.global [%0], [%1], 16;"
                             :: "r"(d), "l"(xg + tid + 512 * i));
            }
            asm volatile("cp.async.commit_group;");
        }

        // pending insert: atomic latency hides under this iter's fma phase
        if (lane == 0 && prow >= 0) hash_insert(prow, pk);

        const float* xsc = cur ? xs1 : xs0;
#pragma unroll
        for (int r = 0; r < P3_RB; r++) {
            const ulonglong2* xp = (const ulonglong2*)(xsc + r * FEATD + k0);
            unsigned long long a0 = 0ull, a1 = 0ull;   // (0.f,0.f) packed
#pragma unroll
            for (int i = 0; i < P3_CH / 4; i++) {
                ulonglong2 v = xp[i];                   // LDS.128 broadcast
                asm("fma.rn.f32x2 %0, %1, %2, %0;"
                    : "+l"(a0) : "l"(v.x), "l"(ppd[2 * i]));
                asm("fma.rn.f32x2 %0, %1, %2, %0;"
                    : "+l"(a1) : "l"(v.y), "l"(ppd[2 * i + 1]));
            }
            unsigned long long at;
            asm("add.rn.f32x2 %0, %1, %2;" : "=l"(at) : "l"(a0), "l"(a1));
            float lo, hi;
            asm("mov.b64 {%0, %1}, %2;" : "=f"(lo), "=f"(hi) : "l"(at));
            psum[(r * P3_NW + warp) * NBINS + lane] = lo + hi;
        }
        __syncthreads();   // psum complete

        // warp w reduces row w across the 16 K-chunks, ballots the key
        float s = 0.f;
#pragma unroll
        for (int c = 0; c < P3_NW; c++)
            s += psum[(warp * P3_NW + c) * NBINS + lane];
        pk = __ballot_sync(0xffffffffu, s > sbias[lane]);
        prow = batch * P3_RB + warp;

        if (nb < P3_NBATCH)
            asm volatile("cp.async.wait_group 0;" ::: "memory");
        __syncthreads();   // next tile visible + psum WAR-safe
        cur ^= 1;
    }
    // flush last pending insert
    if (lane == 0 && prow >= 0) hash_insert(prow, pk);
}

// ---------------------------------------------------------------------------
// Kernel 5: emit rewards for unique keys (count==1 -> 1.0); collect dup rows.
// ---------------------------------------------------------------------------
__global__ void __launch_bounds__(256) emit_kernel(float* __restrict__ out) {
    int i = blockIdx.x * 256 + threadIdx.x;
    if (g_hcnt[g_slot[i]] == 1u) {
        out[i] = 1.0f;
    } else {
        int d = atomicAdd(&g_dupn, 1);
        if (d < DUP_CAP) g_dup[d] = i;
    }
}

// ---------------------------------------------------------------------------
// Kernel 6: exact occurrence rank for duplicated rows (rare; ~2 expected).
// ---------------------------------------------------------------------------
__global__ void __launch_bounds__(256) dupfix_kernel(float* __restrict__ out) {
    __shared__ int red[256];
    int n = g_dupn;
    if (n > DUP_CAP) n = DUP_CAP;
    int t = threadIdx.x;
    for (int d = blockIdx.x; d < n; d += gridDim.x) {
        int i = g_dup[d];
        unsigned key = g_keys[i];
        int c = 0;
        for (int j = t; j <= i; j += 256) c += (g_keys[j] == key) ? 1 : 0;
        red[t] = c;
        __syncthreads();
#pragma unroll
        for (int off = 128; off > 0; off >>= 1) {
            if (t < off) red[t] += red[t + off];
            __syncthreads();
        }
        if (t == 0) out[i] = rsqrtf((float)red[0]);
        __syncthreads();   // red reuse guard
    }
}

// ---------------------------------------------------------------------------
extern "C" void kernel_launch(void* const* d_in, const int* in_sizes, int n_in,
                              void* d_out, int out_size) {
    const float* x = (const float*)d_in[0];   // features  [64,1024,512]
    const float* P = (const float*)d_in[1];   // projection [512,32]
    if (n_in >= 2 && in_sizes[0] < in_sizes[1]) {   // defensive order check
        const float* t = x; x = P; P = t;
    }
    float* out = (float*)d_out;

    cudaFuncSetAttribute(proj_kernel,
                         cudaFuncAttributeMaxDynamicSharedMemorySize, P3_SMEM);

    sums_kernel     <<<1024, 128>>>(x);
    midreduce_kernel<<<16,   512>>>();
    pp_kernel       <<<16,   1024>>>(P);
    proj_kernel     <<<296,  512, P3_SMEM>>>(x);
    emit_kernel     <<<NROWS / 256, 256>>>(out);
    dupfix_kernel   <<<16,   256>>>(out);
}